// round 1
// baseline (speedup 1.0000x reference)
#include <cuda_runtime.h>
#include <math.h>
#include <stdint.h>

// ---------------- problem constants ----------------
#define BATCH   2
#define SEQ     2048
#define DMODEL  2048
#define NHEADS  32
#define DSTATE  64
#define HEADDIM 64
#define DCONV   4
#define INTERSZ 5504
#define DINNER  DMODEL
#define CONVDIM (DINNER + 2*NHEADS*DSTATE)              /* 6144 */
#define DPROJ   (2*DINNER + 2*NHEADS*DSTATE + NHEADS)   /* 8224 */
#define MROWS   (BATCH*SEQ)                             /* 4096 */

// ---------------- scratch (static device allocations only) ----------------
__device__ float g_xnorm[(size_t)MROWS * DMODEL];
__device__ float g_zx   [(size_t)MROWS * DPROJ];
__device__ float g_xbc  [(size_t)MROWS * CONVDIM];
__device__ float g_gated[(size_t)MROWS * DMODEL];
__device__ float g_res2 [(size_t)MROWS * DMODEL];
__device__ float g_h2n  [(size_t)MROWS * DMODEL];
__device__ float g_gate [(size_t)MROWS * INTERSZ];
__device__ float g_up   [(size_t)MROWS * INTERSZ];

// ---------------- RMSNorm (optionally * mask) ----------------
__global__ void rmsnorm_kernel(const float* __restrict__ x,
                               const float* __restrict__ w,
                               const float* __restrict__ mask,
                               float* __restrict__ out)
{
    const int m = blockIdx.x;
    const float* row = x + (size_t)m * DMODEL;
    float s = 0.f;
    for (int i = threadIdx.x; i < DMODEL; i += 256) { float v = row[i]; s += v * v; }
#pragma unroll
    for (int o = 16; o > 0; o >>= 1) s += __shfl_xor_sync(0xffffffffu, s, o);
    __shared__ float red[8];
    const int lane = threadIdx.x & 31, wid = threadIdx.x >> 5;
    if (lane == 0) red[wid] = s;
    __syncthreads();
    if (wid == 0) {
        s = (lane < 8) ? red[lane] : 0.f;
#pragma unroll
        for (int o = 4; o > 0; o >>= 1) s += __shfl_xor_sync(0xffffffffu, s, o);
        if (lane == 0) red[0] = s;
    }
    __syncthreads();
    const float inv = rsqrtf(red[0] * (1.0f / (float)DMODEL) + 1e-6f);
    const float mk = mask ? mask[m] : 1.f;
    for (int i = threadIdx.x; i < DMODEL; i += 256)
        out[(size_t)m * DMODEL + i] = row[i] * inv * w[i] * mk;
}

// ---------------- SGEMM NT: C[m,n] = sum_k A[m,k]*B[n,k] (+ add) ----------------
// A: MxK row-major, B: NxK row-major. M multiple of 128, K multiple of 8.
#define BM 128
#define BN 128
#define BKK 8
__global__ __launch_bounds__(256) void sgemm_nt(
    const float* __restrict__ A, const float* __restrict__ Bw,
    float* __restrict__ C, int M, int N, int K,
    const float* __restrict__ addv, int addflag)
{
    __shared__ float As[2][BKK][BM];
    __shared__ float Bs[2][BKK][BN];
    const int tid = threadIdx.x;
    const int bm = blockIdx.y * BM;
    const int bn = blockIdx.x * BN;

    const int lr = tid >> 1;          // 0..127
    const int lc = (tid & 1) << 2;    // 0 or 4

    const int tx = tid & 15;
    const int ty = tid >> 4;

    float acc[8][8];
#pragma unroll
    for (int i = 0; i < 8; i++)
#pragma unroll
        for (int j = 0; j < 8; j++) acc[i][j] = 0.f;

    const float* Aptr = A + (size_t)(bm + lr) * K + lc;
    const bool brow_ok = (bn + lr) < N;
    const float* Bptr = Bw + (size_t)(bn + lr) * K + lc;

    float4 av = *(const float4*)Aptr;
    float4 bv = brow_ok ? *(const float4*)Bptr : make_float4(0.f, 0.f, 0.f, 0.f);
    As[0][lc + 0][lr] = av.x; As[0][lc + 1][lr] = av.y;
    As[0][lc + 2][lr] = av.z; As[0][lc + 3][lr] = av.w;
    Bs[0][lc + 0][lr] = bv.x; Bs[0][lc + 1][lr] = bv.y;
    Bs[0][lc + 2][lr] = bv.z; Bs[0][lc + 3][lr] = bv.w;
    __syncthreads();

    const int nslab = K / BKK;
    for (int s = 0; s < nslab; ++s) {
        const int cur = s & 1;
        const bool pre = (s + 1 < nslab);
        if (pre) {
            av = *(const float4*)(Aptr + (size_t)(s + 1) * BKK);
            bv = brow_ok ? *(const float4*)(Bptr + (size_t)(s + 1) * BKK)
                         : make_float4(0.f, 0.f, 0.f, 0.f);
        }
#pragma unroll
        for (int k = 0; k < BKK; k++) {
            float ar[8], br[8];
            *(float4*)&ar[0] = *(const float4*)&As[cur][k][ty * 4];
            *(float4*)&ar[4] = *(const float4*)&As[cur][k][64 + ty * 4];
            *(float4*)&br[0] = *(const float4*)&Bs[cur][k][tx * 4];
            *(float4*)&br[4] = *(const float4*)&Bs[cur][k][64 + tx * 4];
#pragma unroll
            for (int i = 0; i < 8; i++)
#pragma unroll
                for (int j = 0; j < 8; j++)
                    acc[i][j] = fmaf(ar[i], br[j], acc[i][j]);
        }
        if (pre) {
            const int nxt = cur ^ 1;
            As[nxt][lc + 0][lr] = av.x; As[nxt][lc + 1][lr] = av.y;
            As[nxt][lc + 2][lr] = av.z; As[nxt][lc + 3][lr] = av.w;
            Bs[nxt][lc + 0][lr] = bv.x; Bs[nxt][lc + 1][lr] = bv.y;
            Bs[nxt][lc + 2][lr] = bv.z; Bs[nxt][lc + 3][lr] = bv.w;
        }
        __syncthreads();
    }

#pragma unroll
    for (int i = 0; i < 8; i++) {
        const int m = bm + ((i < 4) ? (ty * 4 + i) : (64 + ty * 4 + (i - 4)));
#pragma unroll
        for (int j = 0; j < 8; j++) {
            const int n = bn + ((j < 4) ? (tx * 4 + j) : (64 + tx * 4 + (j - 4)));
            if (n < N) {
                const size_t idx = (size_t)m * N + n;
                float v = acc[i][j];
                if (addflag) v += addv[idx];
                C[idx] = v;
            }
        }
    }
}

// ---------------- causal depthwise conv1d over xBC channels ----------------
__global__ void conv_kernel(const float* __restrict__ zx,
                            const float* __restrict__ cw,
                            const float* __restrict__ cb,
                            float* __restrict__ xbc)
{
    const int m = blockIdx.x;          // 0..MROWS-1
    const int t = m & (SEQ - 1);
    for (int c = threadIdx.x; c < CONVDIM; c += 256) {
        float acc = cb[c];
#pragma unroll
        for (int j = 0; j < DCONV; j++) {
            const int tt = t - (DCONV - 1) + j;
            if (tt >= 0)
                acc += cw[c * DCONV + j] *
                       zx[(size_t)(m - (DCONV - 1) + j) * DPROJ + DINNER + c];
        }
        xbc[(size_t)m * CONVDIM + c] = acc;
    }
}

// ---------------- sequential SSM scan, fused with +D*x and silu(z) gating ----------------
// one block per (b,h); 256 threads: 4 lanes per p-row, 16 states each.
// per-timestep shared layout (257 floats): [x:0..63 | B:64..127 | C:128..191 | z:192..255 | a:256]
#define CHK 8
#define TVALS 257
__global__ __launch_bounds__(256) void scan_kernel(
    const float* __restrict__ xbc, const float* __restrict__ zx,
    const float* __restrict__ Dv, const float* __restrict__ zb,
    float* __restrict__ gated)
{
    const int bh = blockIdx.x;
    const int b = bh >> 5;
    const int h = bh & 31;
    const int tid = threadIdx.x;
    const int p = tid >> 2;
    const int q = tid & 3;
    const int n0 = q << 4;

    __shared__ float sd[2][CHK * TVALS];

    // loader mapping: flat element e = tid + 256*k  →  (tsub, kind, col)
    int lts[9], loff[9], lkind[9], lsh[9];
    bool lvalid[9];
#pragma unroll
    for (int k = 0; k < 9; k++) {
        const int e = tid + k * 256;
        lvalid[k] = (e < CHK * TVALS);
        const int tsub = e / TVALS;
        const int j = e - tsub * TVALS;
        lts[k] = tsub; lsh[k] = e;
        if (j < 64)        { lkind[k] = 0; loff[k] = h * HEADDIM + j; }
        else if (j < 128)  { lkind[k] = 0; loff[k] = DINNER + h * DSTATE + (j - 64); }
        else if (j < 192)  { lkind[k] = 0; loff[k] = DINNER + NHEADS * DSTATE + h * DSTATE + (j - 128); }
        else if (j < 256)  { lkind[k] = 1; loff[k] = h * HEADDIM + (j - 192); }     // z from zxbcdt
        else               { lkind[k] = 2; loff[k] = 2 * DINNER + 2 * NHEADS * DSTATE + h; } // A_log
    }

    // prologue: load chunk 0 directly to shared
#pragma unroll
    for (int k = 0; k < 9; k++) {
        if (lvalid[k]) {
            const size_t m = (size_t)b * SEQ + lts[k];
            float v;
            if (lkind[k] == 0) v = xbc[m * CONVDIM + loff[k]];
            else               v = zx[m * DPROJ + loff[k]];
            if (lkind[k] == 2) v = 1.f / (1.f + expf(v));  // exp(-softplus(A_log))
            sd[0][lsh[k]] = v;
        }
    }
    __syncthreads();

    float st[16];
#pragma unroll
    for (int i = 0; i < 16; i++) st[i] = 0.f;

    const float Dh = Dv[h];
    const float zbias = zb[h * HEADDIM + p];

    const int NC = SEQ / CHK;
    for (int c = 0; c < NC; c++) {
        const int cur = c & 1;
        const bool pre = (c + 1 < NC);
        float regv[9];
        if (pre) {
#pragma unroll
            for (int k = 0; k < 9; k++) {
                if (lvalid[k]) {
                    const size_t m = (size_t)b * SEQ + (c + 1) * CHK + lts[k];
                    float v;
                    if (lkind[k] == 0) v = xbc[m * CONVDIM + loff[k]];
                    else               v = zx[m * DPROJ + loff[k]];
                    if (lkind[k] == 2) v = 1.f / (1.f + expf(v));
                    regv[k] = v;
                }
            }
        }
        const float* dbase = sd[cur];
#pragma unroll
        for (int tsub = 0; tsub < CHK; tsub++) {
            const float* dd = dbase + tsub * TVALS;
            const float a  = dd[256];
            const float xv = dd[p];
            float y = 0.f;
#pragma unroll
            for (int i = 0; i < 16; i++) {
                st[i] = a * st[i] + xv * dd[64 + n0 + i];
                y = fmaf(st[i], dd[128 + n0 + i], y);
            }
            y += __shfl_xor_sync(0xffffffffu, y, 1);
            y += __shfl_xor_sync(0xffffffffu, y, 2);
            if (q == 0) {
                const size_t m = (size_t)b * SEQ + c * CHK + tsub;
                const float zval = dd[192 + p] + zbias;
                const float sig = 1.f / (1.f + expf(-zval));
                gated[m * DMODEL + h * HEADDIM + p] = (y + Dh * xv) * (zval * sig);
            }
        }
        if (pre) {
#pragma unroll
            for (int k = 0; k < 9; k++)
                if (lvalid[k]) sd[cur ^ 1][lsh[k]] = regv[k];
        }
        __syncthreads();
    }
}

// ---------------- silu(gate) * up, in place on gate ----------------
__global__ void silumul_kernel(float* __restrict__ g, const float* __restrict__ u, size_t n)
{
    size_t i = (size_t)blockIdx.x * blockDim.x + threadIdx.x;
    const size_t stride = (size_t)gridDim.x * blockDim.x;
    for (; i < n; i += stride) {
        const float x = g[i];
        g[i] = u[i] * x / (1.f + expf(-x));
    }
}

// ---------------- launcher ----------------
extern "C" void kernel_launch(void* const* d_in, const int* in_sizes, int n_in,
                              void* d_out, int out_size)
{
    (void)in_sizes; (void)n_in; (void)out_size;
    const float* hidden    = (const float*)d_in[0];
    const float* mask      = (const float*)d_in[1];
    const float* in_proj_w = (const float*)d_in[2];
    const float* conv_w    = (const float*)d_in[3];
    const float* conv_b    = (const float*)d_in[4];
    const float* z_bias    = (const float*)d_in[5];
    const float* Dv        = (const float*)d_in[6];
    const float* out_proj_w= (const float*)d_in[7];
    const float* ln1_w     = (const float*)d_in[8];
    const float* ln2_w     = (const float*)d_in[9];
    const float* gate_w    = (const float*)d_in[10];
    const float* up_w      = (const float*)d_in[11];
    const float* down_w    = (const float*)d_in[12];
    float* out = (float*)d_out;

    float *xnorm, *zx, *xbc, *gated, *res2, *h2n, *gateb, *upb;
    cudaGetSymbolAddress((void**)&xnorm, g_xnorm);
    cudaGetSymbolAddress((void**)&zx,    g_zx);
    cudaGetSymbolAddress((void**)&xbc,   g_xbc);
    cudaGetSymbolAddress((void**)&gated, g_gated);
    cudaGetSymbolAddress((void**)&res2,  g_res2);
    cudaGetSymbolAddress((void**)&h2n,   g_h2n);
    cudaGetSymbolAddress((void**)&gateb, g_gate);
    cudaGetSymbolAddress((void**)&upb,   g_up);

    // 1. rmsnorm(hidden, ln1) * mask
    rmsnorm_kernel<<<MROWS, 256>>>(hidden, ln1_w, mask, xnorm);

    // 2. zxbcdt = xnorm @ in_proj_w^T   (4096 x 8224 x 2048)
    sgemm_nt<<<dim3((DPROJ + BN - 1) / BN, MROWS / BM), 256>>>(
        xnorm, in_proj_w, zx, MROWS, DPROJ, DMODEL, nullptr, 0);

    // 3. causal depthwise conv over xBC slice + bias
    conv_kernel<<<MROWS, 256>>>(zx, conv_w, conv_b, xbc);

    // 4. SSM scan fused with +D*x and silu(z) gating → gated
    scan_kernel<<<BATCH * NHEADS, 256>>>(xbc, zx, Dv, z_bias, gated);

    // 5. res2 = gated @ out_proj_w^T + hidden
    sgemm_nt<<<dim3(DMODEL / BN, MROWS / BM), 256>>>(
        gated, out_proj_w, res2, MROWS, DMODEL, DMODEL, hidden, 1);

    // 6. h2n = rmsnorm(res2, ln2)
    rmsnorm_kernel<<<MROWS, 256>>>(res2, ln2_w, nullptr, h2n);

    // 7/8. gate and up projections (4096 x 5504 x 2048)
    sgemm_nt<<<dim3(INTERSZ / BN, MROWS / BM), 256>>>(
        h2n, gate_w, gateb, MROWS, INTERSZ, DMODEL, nullptr, 0);
    sgemm_nt<<<dim3(INTERSZ / BN, MROWS / BM), 256>>>(
        h2n, up_w, upb, MROWS, INTERSZ, DMODEL, nullptr, 0);

    // 9. gate = silu(gate) * up
    silumul_kernel<<<8192, 256>>>(gateb, upb, (size_t)MROWS * INTERSZ);

    // 10. out = gate @ down_w^T + res2   (4096 x 2048 x 5504)
    sgemm_nt<<<dim3(DMODEL / BN, MROWS / BM), 256>>>(
        gateb, down_w, out, MROWS, DMODEL, INTERSZ, res2, 1);
}

// round 2
// speedup vs baseline: 1.0059x; 1.0059x over previous
#include <cuda_runtime.h>
#include <math.h>
#include <stdint.h>

// ---------------- problem constants ----------------
#define BATCH   2
#define SEQ     2048
#define DMODEL  2048
#define NHEADS  32
#define DSTATE  64
#define HEADDIM 64
#define DCONV   4
#define INTERSZ 5504
#define DINNER  DMODEL
#define CONVDIM (DINNER + 2*NHEADS*DSTATE)              /* 6144 */
#define DPROJ   (2*DINNER + 2*NHEADS*DSTATE + NHEADS)   /* 8224 */
#define MROWS   (BATCH*SEQ)                             /* 4096 */

// ---------------- scratch (static device allocations only) ----------------
__device__ float g_xnorm[(size_t)MROWS * DMODEL];
__device__ float g_zx   [(size_t)MROWS * DPROJ];
__device__ float g_xbc  [(size_t)MROWS * CONVDIM];
__device__ float g_gated[(size_t)MROWS * DMODEL];
__device__ float g_res2 [(size_t)MROWS * DMODEL];
__device__ float g_h2n  [(size_t)MROWS * DMODEL];
__device__ float g_gate [(size_t)MROWS * INTERSZ];
__device__ float g_up   [(size_t)MROWS * INTERSZ];

// ---------------- RMSNorm (optionally * mask) ----------------
__global__ void rmsnorm_kernel(const float* __restrict__ x,
                               const float* __restrict__ w,
                               const float* __restrict__ mask,
                               float* __restrict__ out)
{
    const int m = blockIdx.x;
    const float* row = x + (size_t)m * DMODEL;
    float s = 0.f;
    for (int i = threadIdx.x; i < DMODEL; i += 256) { float v = row[i]; s += v * v; }
#pragma unroll
    for (int o = 16; o > 0; o >>= 1) s += __shfl_xor_sync(0xffffffffu, s, o);
    __shared__ float red[8];
    const int lane = threadIdx.x & 31, wid = threadIdx.x >> 5;
    if (lane == 0) red[wid] = s;
    __syncthreads();
    if (wid == 0) {
        s = (lane < 8) ? red[lane] : 0.f;
#pragma unroll
        for (int o = 4; o > 0; o >>= 1) s += __shfl_xor_sync(0xffffffffu, s, o);
        if (lane == 0) red[0] = s;
    }
    __syncthreads();
    const float inv = rsqrtf(red[0] * (1.0f / (float)DMODEL) + 1e-6f);
    const float mk = mask ? mask[m] : 1.f;
    for (int i = threadIdx.x; i < DMODEL; i += 256)
        out[(size_t)m * DMODEL + i] = row[i] * inv * w[i] * mk;
}

// ---------------- SGEMM NT: C[m,n] = sum_k A[m,k]*B[n,k] (+ add) ----------------
// A: MxK row-major, B: NxK row-major. M multiple of 128, K multiple of 8.
#define BM 128
#define BN 128
#define BKK 8
__global__ __launch_bounds__(256) void sgemm_nt(
    const float* __restrict__ A, const float* __restrict__ Bw,
    float* __restrict__ C, int M, int N, int K,
    const float* __restrict__ addv, int addflag)
{
    __shared__ float As[2][BKK][BM];
    __shared__ float Bs[2][BKK][BN];
    const int tid = threadIdx.x;
    const int bm = blockIdx.y * BM;
    const int bn = blockIdx.x * BN;

    const int lr = tid >> 1;          // 0..127
    const int lc = (tid & 1) << 2;    // 0 or 4

    const int tx = tid & 15;
    const int ty = tid >> 4;

    float acc[8][8];
#pragma unroll
    for (int i = 0; i < 8; i++)
#pragma unroll
        for (int j = 0; j < 8; j++) acc[i][j] = 0.f;

    const float* Aptr = A + (size_t)(bm + lr) * K + lc;
    const bool brow_ok = (bn + lr) < N;
    const float* Bptr = Bw + (size_t)(bn + lr) * K + lc;

    float4 av = *(const float4*)Aptr;
    float4 bv = brow_ok ? *(const float4*)Bptr : make_float4(0.f, 0.f, 0.f, 0.f);
    As[0][lc + 0][lr] = av.x; As[0][lc + 1][lr] = av.y;
    As[0][lc + 2][lr] = av.z; As[0][lc + 3][lr] = av.w;
    Bs[0][lc + 0][lr] = bv.x; Bs[0][lc + 1][lr] = bv.y;
    Bs[0][lc + 2][lr] = bv.z; Bs[0][lc + 3][lr] = bv.w;
    __syncthreads();

    const int nslab = K / BKK;
    for (int s = 0; s < nslab; ++s) {
        const int cur = s & 1;
        const bool pre = (s + 1 < nslab);
        if (pre) {
            av = *(const float4*)(Aptr + (size_t)(s + 1) * BKK);
            bv = brow_ok ? *(const float4*)(Bptr + (size_t)(s + 1) * BKK)
                         : make_float4(0.f, 0.f, 0.f, 0.f);
        }
#pragma unroll
        for (int k = 0; k < BKK; k++) {
            float ar[8], br[8];
            *(float4*)&ar[0] = *(const float4*)&As[cur][k][ty * 4];
            *(float4*)&ar[4] = *(const float4*)&As[cur][k][64 + ty * 4];
            *(float4*)&br[0] = *(const float4*)&Bs[cur][k][tx * 4];
            *(float4*)&br[4] = *(const float4*)&Bs[cur][k][64 + tx * 4];
#pragma unroll
            for (int i = 0; i < 8; i++)
#pragma unroll
                for (int j = 0; j < 8; j++)
                    acc[i][j] = fmaf(ar[i], br[j], acc[i][j]);
        }
        if (pre) {
            const int nxt = cur ^ 1;
            As[nxt][lc + 0][lr] = av.x; As[nxt][lc + 1][lr] = av.y;
            As[nxt][lc + 2][lr] = av.z; As[nxt][lc + 3][lr] = av.w;
            Bs[nxt][lc + 0][lr] = bv.x; Bs[nxt][lc + 1][lr] = bv.y;
            Bs[nxt][lc + 2][lr] = bv.z; Bs[nxt][lc + 3][lr] = bv.w;
        }
        __syncthreads();
    }

#pragma unroll
    for (int i = 0; i < 8; i++) {
        const int m = bm + ((i < 4) ? (ty * 4 + i) : (64 + ty * 4 + (i - 4)));
#pragma unroll
        for (int j = 0; j < 8; j++) {
            const int n = bn + ((j < 4) ? (tx * 4 + j) : (64 + tx * 4 + (j - 4)));
            if (n < N) {
                const size_t idx = (size_t)m * N + n;
                float v = acc[i][j];
                if (addflag) v += addv[idx];
                C[idx] = v;
            }
        }
    }
}

// ---------------- causal depthwise conv1d over xBC channels ----------------
__global__ void conv_kernel(const float* __restrict__ zx,
                            const float* __restrict__ cw,
                            const float* __restrict__ cb,
                            float* __restrict__ xbc)
{
    const int m = blockIdx.x;          // 0..MROWS-1
    const int t = m & (SEQ - 1);
    for (int c = threadIdx.x; c < CONVDIM; c += 256) {
        float acc = cb[c];
#pragma unroll
        for (int j = 0; j < DCONV; j++) {
            const int tt = t - (DCONV - 1) + j;
            if (tt >= 0)
                acc += cw[c * DCONV + j] *
                       zx[(size_t)(m - (DCONV - 1) + j) * DPROJ + DINNER + c];
        }
        xbc[(size_t)m * CONVDIM + c] = acc;
    }
}

// ---------------- sequential SSM scan, fused with +D*x and silu(z) gating ----------------
// one block per (b,h); 256 threads: 4 lanes per p-row, 16 states each.
// per-timestep shared layout (257 floats): [x:0..63 | B:64..127 | C:128..191 | z:192..255 | a:256]
#define CHK 8
#define TVALS 257
__global__ __launch_bounds__(256) void scan_kernel(
    const float* __restrict__ xbc, const float* __restrict__ zx,
    const float* __restrict__ Dv, const float* __restrict__ zb,
    float* __restrict__ gated)
{
    const int bh = blockIdx.x;
    const int b = bh >> 5;
    const int h = bh & 31;
    const int tid = threadIdx.x;
    const int p = tid >> 2;
    const int q = tid & 3;
    const int n0 = q << 4;

    __shared__ float sd[2][CHK * TVALS];

    // loader mapping: flat element e = tid + 256*k  →  (tsub, kind, col)
    int lts[9], loff[9], lkind[9], lsh[9];
    bool lvalid[9];
#pragma unroll
    for (int k = 0; k < 9; k++) {
        const int e = tid + k * 256;
        lvalid[k] = (e < CHK * TVALS);
        const int tsub = e / TVALS;
        const int j = e - tsub * TVALS;
        lts[k] = tsub; lsh[k] = e;
        if (j < 64)        { lkind[k] = 0; loff[k] = h * HEADDIM + j; }
        else if (j < 128)  { lkind[k] = 0; loff[k] = DINNER + h * DSTATE + (j - 64); }
        else if (j < 192)  { lkind[k] = 0; loff[k] = DINNER + NHEADS * DSTATE + h * DSTATE + (j - 128); }
        else if (j < 256)  { lkind[k] = 1; loff[k] = h * HEADDIM + (j - 192); }     // z from zxbcdt
        else               { lkind[k] = 2; loff[k] = 2 * DINNER + 2 * NHEADS * DSTATE + h; } // A_log
    }

    // prologue: load chunk 0 directly to shared
#pragma unroll
    for (int k = 0; k < 9; k++) {
        if (lvalid[k]) {
            const size_t m = (size_t)b * SEQ + lts[k];
            float v;
            if (lkind[k] == 0) v = xbc[m * CONVDIM + loff[k]];
            else               v = zx[m * DPROJ + loff[k]];
            if (lkind[k] == 2) v = 1.f / (1.f + expf(v));  // exp(-softplus(A_log))
            sd[0][lsh[k]] = v;
        }
    }
    __syncthreads();

    float st[16];
#pragma unroll
    for (int i = 0; i < 16; i++) st[i] = 0.f;

    const float Dh = Dv[h];
    const float zbias = zb[h * HEADDIM + p];

    const int NC = SEQ / CHK;
    for (int c = 0; c < NC; c++) {
        const int cur = c & 1;
        const bool pre = (c + 1 < NC);
        float regv[9];
        if (pre) {
#pragma unroll
            for (int k = 0; k < 9; k++) {
                if (lvalid[k]) {
                    const size_t m = (size_t)b * SEQ + (c + 1) * CHK + lts[k];
                    float v;
                    if (lkind[k] == 0) v = xbc[m * CONVDIM + loff[k]];
                    else               v = zx[m * DPROJ + loff[k]];
                    if (lkind[k] == 2) v = 1.f / (1.f + expf(v));
                    regv[k] = v;
                }
            }
        }
        const float* dbase = sd[cur];
#pragma unroll
        for (int tsub = 0; tsub < CHK; tsub++) {
            const float* dd = dbase + tsub * TVALS;
            const float a  = dd[256];
            const float xv = dd[p];
            float y = 0.f;
#pragma unroll
            for (int i = 0; i < 16; i++) {
                st[i] = a * st[i] + xv * dd[64 + n0 + i];
                y = fmaf(st[i], dd[128 + n0 + i], y);
            }
            y += __shfl_xor_sync(0xffffffffu, y, 1);
            y += __shfl_xor_sync(0xffffffffu, y, 2);
            if (q == 0) {
                const size_t m = (size_t)b * SEQ + c * CHK + tsub;
                const float zval = dd[192 + p] + zbias;
                const float sig = 1.f / (1.f + expf(-zval));
                gated[m * DMODEL + h * HEADDIM + p] = (y + Dh * xv) * (zval * sig);
            }
        }
        if (pre) {
#pragma unroll
            for (int k = 0; k < 9; k++)
                if (lvalid[k]) sd[cur ^ 1][lsh[k]] = regv[k];
        }
        __syncthreads();
    }
}

// ---------------- silu(gate) * up, in place on gate ----------------
__global__ void silumul_kernel(float* __restrict__ g, const float* __restrict__ u, size_t n)
{
    size_t i = (size_t)blockIdx.x * blockDim.x + threadIdx.x;
    const size_t stride = (size_t)gridDim.x * blockDim.x;
    for (; i < n; i += stride) {
        const float x = g[i];
        g[i] = u[i] * x / (1.f + expf(-x));
    }
}

// ---------------- launcher ----------------
extern "C" void kernel_launch(void* const* d_in, const int* in_sizes, int n_in,
                              void* d_out, int out_size)
{
    (void)in_sizes; (void)n_in; (void)out_size;
    const float* hidden    = (const float*)d_in[0];
    const float* mask      = (const float*)d_in[1];
    const float* in_proj_w = (const float*)d_in[2];
    const float* conv_w    = (const float*)d_in[3];
    const float* conv_b    = (const float*)d_in[4];
    const float* z_bias    = (const float*)d_in[5];
    const float* Dv        = (const float*)d_in[6];
    const float* out_proj_w= (const float*)d_in[7];
    const float* ln1_w     = (const float*)d_in[8];
    const float* ln2_w     = (const float*)d_in[9];
    const float* gate_w    = (const float*)d_in[10];
    const float* up_w      = (const float*)d_in[11];
    const float* down_w    = (const float*)d_in[12];
    float* out = (float*)d_out;

    float *xnorm, *zx, *xbc, *gated, *res2, *h2n, *gateb, *upb;
    cudaGetSymbolAddress((void**)&xnorm, g_xnorm);
    cudaGetSymbolAddress((void**)&zx,    g_zx);
    cudaGetSymbolAddress((void**)&xbc,   g_xbc);
    cudaGetSymbolAddress((void**)&gated, g_gated);
    cudaGetSymbolAddress((void**)&res2,  g_res2);
    cudaGetSymbolAddress((void**)&h2n,   g_h2n);
    cudaGetSymbolAddress((void**)&gateb, g_gate);
    cudaGetSymbolAddress((void**)&upb,   g_up);

    // 1. rmsnorm(hidden, ln1) * mask
    rmsnorm_kernel<<<MROWS, 256>>>(hidden, ln1_w, mask, xnorm);

    // 2. zxbcdt = xnorm @ in_proj_w^T   (4096 x 8224 x 2048)
    sgemm_nt<<<dim3((DPROJ + BN - 1) / BN, MROWS / BM), 256>>>(
        xnorm, in_proj_w, zx, MROWS, DPROJ, DMODEL, nullptr, 0);

    // 3. causal depthwise conv over xBC slice + bias
    conv_kernel<<<MROWS, 256>>>(zx, conv_w, conv_b, xbc);

    // 4. SSM scan fused with +D*x and silu(z) gating → gated
    scan_kernel<<<BATCH * NHEADS, 256>>>(xbc, zx, Dv, z_bias, gated);

    // 5. res2 = gated @ out_proj_w^T + hidden
    sgemm_nt<<<dim3(DMODEL / BN, MROWS / BM), 256>>>(
        gated, out_proj_w, res2, MROWS, DMODEL, DMODEL, hidden, 1);

    // 6. h2n = rmsnorm(res2, ln2)
    rmsnorm_kernel<<<MROWS, 256>>>(res2, ln2_w, nullptr, h2n);

    // 7/8. gate and up projections (4096 x 5504 x 2048)
    sgemm_nt<<<dim3(INTERSZ / BN, MROWS / BM), 256>>>(
        h2n, gate_w, gateb, MROWS, INTERSZ, DMODEL, nullptr, 0);
    sgemm_nt<<<dim3(INTERSZ / BN, MROWS / BM), 256>>>(
        h2n, up_w, upb, MROWS, INTERSZ, DMODEL, nullptr, 0);

    // 9. gate = silu(gate) * up
    silumul_kernel<<<8192, 256>>>(gateb, upb, (size_t)MROWS * INTERSZ);

    // 10. out = gate @ down_w^T + res2   (4096 x 2048 x 5504)
    sgemm_nt<<<dim3(DMODEL / BN, MROWS / BM), 256>>>(
        gateb, down_w, out, MROWS, DMODEL, INTERSZ, res2, 1);
}

// round 4
// speedup vs baseline: 1.7329x; 1.7226x over previous
#include <cuda_runtime.h>
#include <cuda_bf16.h>
#include <math.h>
#include <stdint.h>

#define BATCH   2
#define SEQ     2048
#define DMODEL  2048
#define NHEADS  32
#define DSTATE  64
#define HEADDIM 64
#define DCONV   4
#define INTERSZ 5504
#define DINNER  DMODEL
#define CONVDIM (DINNER + 2*NHEADS*DSTATE)              /* 6144 */
#define DPROJ   (2*DINNER + 2*NHEADS*DSTATE + NHEADS)   /* 8224 */
#define MROWS   (BATCH*SEQ)                             /* 4096 */

// ---------------- scratch ----------------
__device__ float g_xnorm[(size_t)MROWS * DMODEL];
__device__ float g_zx   [(size_t)MROWS * DPROJ];
__device__ float g_xbc  [(size_t)MROWS * CONVDIM];
__device__ float g_gated[(size_t)MROWS * DMODEL];
__device__ float g_res2 [(size_t)MROWS * DMODEL];
__device__ float g_gatef[(size_t)MROWS * INTERSZ];
__device__ float g_upf  [(size_t)MROWS * INTERSZ];

static __device__ __forceinline__ uint32_t smem_u32(const void* p) {
    uint32_t a;
    asm("{ .reg .u64 t; cvta.to.shared.u64 t, %1; cvt.u32.u64 %0, t; }" : "=r"(a) : "l"(p));
    return a;
}

#define LDSM_X4(r, addr) \
    asm volatile("ldmatrix.sync.aligned.m8n8.x4.shared.b16 {%0,%1,%2,%3}, [%4];" \
        : "=r"((r)[0]), "=r"((r)[1]), "=r"((r)[2]), "=r"((r)[3]) : "r"(addr))

#define MMA16816(c, a, b0, b1) \
    asm volatile("mma.sync.aligned.m16n8k16.row.col.f32.bf16.bf16.f32 " \
        "{%0,%1,%2,%3}, {%4,%5,%6,%7}, {%8,%9}, {%0,%1,%2,%3};" \
        : "+f"((c)[0]), "+f"((c)[1]), "+f"((c)[2]), "+f"((c)[3]) \
        : "r"((a)[0]), "r"((a)[1]), "r"((a)[2]), "r"((a)[3]), "r"(b0), "r"(b1))

// ================= bf16x3 GEMM on mma.sync =================
// C[m,n] = sum_k A[m,k]*B[n,k] (+addv). Tiles 128x128x32.
// smem per stage: 4 planes (Ahi, Alo, Bhi, Blo) of 128 rows x 40 bf16 (80B rows).
#define PLANE 10240
#define STAGE 40960
#define GSMEM (2*STAGE)

__global__ __launch_bounds__(256, 1) void gemm_mma(
    const float* __restrict__ A, const float* __restrict__ Bw,
    float* __restrict__ C, const float* __restrict__ addv,
    int N, int K, int addflag)
{
    extern __shared__ char sm[];
    const int tid  = threadIdx.x;
    const int bm   = blockIdx.x * 128;
    const int bn   = blockIdx.y * 128;
    const int warp = tid >> 5, lane = tid & 31;
    const int wm = warp >> 2, wn = warp & 3;       // 2 x 4 warp grid
    const uint32_t sbase = smem_u32(sm);

    // staging: thread -> (row, col16)
    const int srow = tid >> 1;
    const int scol = (tid & 1) << 4;
    const float* aG = A + (size_t)(bm + srow) * K + scol;
    const bool  bok = (bn + srow) < N;
    const float* bG = Bw + (size_t)(bok ? (bn + srow) : 0) * K + scol;
    const uint32_t stoff = (uint32_t)(srow * 80 + scol * 2);

    float acc[4][4][4];
#pragma unroll
    for (int i = 0; i < 4; i++)
#pragma unroll
        for (int j = 0; j < 4; j++)
#pragma unroll
            for (int r = 0; r < 4; r++) acc[i][j][r] = 0.f;

    float fa[16], fb[16];
    // ---- load k-slab 0 into regs ----
#pragma unroll
    for (int v = 0; v < 4; v++) {
        *(float4*)&fa[v*4] = *(const float4*)(aG + v*4);
        *(float4*)&fb[v*4] = bok ? *(const float4*)(bG + v*4)
                                 : make_float4(0.f,0.f,0.f,0.f);
    }
    // convert + store to stage 0
    {
        const uint32_t st = sbase + stoff;
        uint32_t hi[8], lo[8], bhi[8], blo[8];
#pragma unroll
        for (int j = 0; j < 8; j++) {
            __nv_bfloat162 h = __float22bfloat162_rn(make_float2(fa[2*j], fa[2*j+1]));
            float g0 = __bfloat162float(h.x), g1 = __bfloat162float(h.y);
            __nv_bfloat162 l = __float22bfloat162_rn(make_float2(fa[2*j]-g0, fa[2*j+1]-g1));
            hi[j] = *(uint32_t*)&h; lo[j] = *(uint32_t*)&l;
            __nv_bfloat162 hb = __float22bfloat162_rn(make_float2(fb[2*j], fb[2*j+1]));
            float p0 = __bfloat162float(hb.x), p1 = __bfloat162float(hb.y);
            __nv_bfloat162 lb = __float22bfloat162_rn(make_float2(fb[2*j]-p0, fb[2*j+1]-p1));
            bhi[j] = *(uint32_t*)&hb; blo[j] = *(uint32_t*)&lb;
        }
        asm volatile("st.shared.v4.b32 [%0], {%1,%2,%3,%4};" :: "r"(st),            "r"(hi[0]),"r"(hi[1]),"r"(hi[2]),"r"(hi[3]));
        asm volatile("st.shared.v4.b32 [%0], {%1,%2,%3,%4};" :: "r"(st+16),         "r"(hi[4]),"r"(hi[5]),"r"(hi[6]),"r"(hi[7]));
        asm volatile("st.shared.v4.b32 [%0], {%1,%2,%3,%4};" :: "r"(st+PLANE),      "r"(lo[0]),"r"(lo[1]),"r"(lo[2]),"r"(lo[3]));
        asm volatile("st.shared.v4.b32 [%0], {%1,%2,%3,%4};" :: "r"(st+PLANE+16),   "r"(lo[4]),"r"(lo[5]),"r"(lo[6]),"r"(lo[7]));
        asm volatile("st.shared.v4.b32 [%0], {%1,%2,%3,%4};" :: "r"(st+2*PLANE),    "r"(bhi[0]),"r"(bhi[1]),"r"(bhi[2]),"r"(bhi[3]));
        asm volatile("st.shared.v4.b32 [%0], {%1,%2,%3,%4};" :: "r"(st+2*PLANE+16), "r"(bhi[4]),"r"(bhi[5]),"r"(bhi[6]),"r"(bhi[7]));
        asm volatile("st.shared.v4.b32 [%0], {%1,%2,%3,%4};" :: "r"(st+3*PLANE),    "r"(blo[0]),"r"(blo[1]),"r"(blo[2]),"r"(blo[3]));
        asm volatile("st.shared.v4.b32 [%0], {%1,%2,%3,%4};" :: "r"(st+3*PLANE+16), "r"(blo[4]),"r"(blo[5]),"r"(blo[6]),"r"(blo[7]));
    }
    __syncthreads();

    const int lrow  = lane & 15;
    const int lcolb = (lane >> 4) << 3;
    const int nslab = K / 32;

    for (int s = 0; s < nslab; s++) {
        const uint32_t stb = sbase + (uint32_t)(s & 1) * STAGE;
        const bool pre = (s + 1 < nslab);
        if (pre) {
            const int k0 = (s + 1) * 32;
#pragma unroll
            for (int v = 0; v < 4; v++) {
                *(float4*)&fa[v*4] = *(const float4*)(aG + k0 + v*4);
                *(float4*)&fb[v*4] = bok ? *(const float4*)(bG + k0 + v*4)
                                         : make_float4(0.f,0.f,0.f,0.f);
            }
        }
#pragma unroll
        for (int ks = 0; ks < 2; ks++) {
            const int k0 = ks * 16;
            uint32_t ah[4][4], al[4][4];
#pragma unroll
            for (int mt = 0; mt < 4; mt++) {
                const uint32_t off = (uint32_t)(((wm*64 + mt*16 + lrow) * 40 + k0 + lcolb) * 2);
                LDSM_X4(ah[mt], stb + off);
                LDSM_X4(al[mt], stb + PLANE + off);
            }
            uint32_t bh[2][4], bl[2][4];
#pragma unroll
            for (int bt = 0; bt < 2; bt++) {
                const uint32_t off = (uint32_t)(((wn*32 + bt*16 + lrow) * 40 + k0 + lcolb) * 2);
                LDSM_X4(bh[bt], stb + 2*PLANE + off);
                LDSM_X4(bl[bt], stb + 3*PLANE + off);
            }
#pragma unroll
            for (int mt = 0; mt < 4; mt++)
#pragma unroll
                for (int nt = 0; nt < 4; nt++) {
                    const uint32_t b0h = bh[nt>>1][nt&1], b1h = bh[nt>>1][2+(nt&1)];
                    const uint32_t b0l = bl[nt>>1][nt&1], b1l = bl[nt>>1][2+(nt&1)];
                    MMA16816(acc[mt][nt], ah[mt], b0h, b1h);
                    MMA16816(acc[mt][nt], al[mt], b0h, b1h);
                    MMA16816(acc[mt][nt], ah[mt], b0l, b1l);
                }
        }
        if (pre) {
            const uint32_t st = sbase + (uint32_t)((s + 1) & 1) * STAGE + stoff;
            uint32_t hi[8], lo[8], bhi[8], blo[8];
#pragma unroll
            for (int j = 0; j < 8; j++) {
                __nv_bfloat162 h = __float22bfloat162_rn(make_float2(fa[2*j], fa[2*j+1]));
                float g0 = __bfloat162float(h.x), g1 = __bfloat162float(h.y);
                __nv_bfloat162 l = __float22bfloat162_rn(make_float2(fa[2*j]-g0, fa[2*j+1]-g1));
                hi[j] = *(uint32_t*)&h; lo[j] = *(uint32_t*)&l;
                __nv_bfloat162 hb = __float22bfloat162_rn(make_float2(fb[2*j], fb[2*j+1]));
                float p0 = __bfloat162float(hb.x), p1 = __bfloat162float(hb.y);
                __nv_bfloat162 lb = __float22bfloat162_rn(make_float2(fb[2*j]-p0, fb[2*j+1]-p1));
                bhi[j] = *(uint32_t*)&hb; blo[j] = *(uint32_t*)&lb;
            }
            asm volatile("st.shared.v4.b32 [%0], {%1,%2,%3,%4};" :: "r"(st),            "r"(hi[0]),"r"(hi[1]),"r"(hi[2]),"r"(hi[3]));
            asm volatile("st.shared.v4.b32 [%0], {%1,%2,%3,%4};" :: "r"(st+16),         "r"(hi[4]),"r"(hi[5]),"r"(hi[6]),"r"(hi[7]));
            asm volatile("st.shared.v4.b32 [%0], {%1,%2,%3,%4};" :: "r"(st+PLANE),      "r"(lo[0]),"r"(lo[1]),"r"(lo[2]),"r"(lo[3]));
            asm volatile("st.shared.v4.b32 [%0], {%1,%2,%3,%4};" :: "r"(st+PLANE+16),   "r"(lo[4]),"r"(lo[5]),"r"(lo[6]),"r"(lo[7]));
            asm volatile("st.shared.v4.b32 [%0], {%1,%2,%3,%4};" :: "r"(st+2*PLANE),    "r"(bhi[0]),"r"(bhi[1]),"r"(bhi[2]),"r"(bhi[3]));
            asm volatile("st.shared.v4.b32 [%0], {%1,%2,%3,%4};" :: "r"(st+2*PLANE+16), "r"(bhi[4]),"r"(bhi[5]),"r"(bhi[6]),"r"(bhi[7]));
            asm volatile("st.shared.v4.b32 [%0], {%1,%2,%3,%4};" :: "r"(st+3*PLANE),    "r"(blo[0]),"r"(blo[1]),"r"(blo[2]),"r"(blo[3]));
            asm volatile("st.shared.v4.b32 [%0], {%1,%2,%3,%4};" :: "r"(st+3*PLANE+16), "r"(blo[4]),"r"(blo[5]),"r"(blo[6]),"r"(blo[7]));
        }
        __syncthreads();
    }

    // ---- epilogue ----
    const int g  = lane >> 2;
    const int t4 = lane & 3;
#pragma unroll
    for (int mt = 0; mt < 4; mt++) {
        const int row = bm + wm*64 + mt*16 + g;
#pragma unroll
        for (int nt = 0; nt < 4; nt++) {
            const int col = bn + wn*32 + nt*8 + t4*2;
            if (col < N) {
                float2 v0 = make_float2(acc[mt][nt][0], acc[mt][nt][1]);
                float2 v1 = make_float2(acc[mt][nt][2], acc[mt][nt][3]);
                const size_t i0 = (size_t)row * N + col;
                const size_t i1 = (size_t)(row + 8) * N + col;
                if (addflag) {
                    const float2 a0 = *(const float2*)(addv + i0);
                    const float2 a1 = *(const float2*)(addv + i1);
                    v0.x += a0.x; v0.y += a0.y; v1.x += a1.x; v1.y += a1.y;
                }
                *(float2*)(C + i0) = v0;
                *(float2*)(C + i1) = v1;
            }
        }
    }
}

// ---------------- RMSNorm (optionally * mask) ----------------
__global__ void rmsnorm_kernel(const float* __restrict__ x,
                               const float* __restrict__ w,
                               const float* __restrict__ mask,
                               float* __restrict__ out)
{
    const int m = blockIdx.x;
    const float* row = x + (size_t)m * DMODEL;
    float s = 0.f;
    for (int i = threadIdx.x; i < DMODEL; i += 256) { float v = row[i]; s += v * v; }
#pragma unroll
    for (int o = 16; o > 0; o >>= 1) s += __shfl_xor_sync(0xffffffffu, s, o);
    __shared__ float red[8];
    const int lane = threadIdx.x & 31, wid = threadIdx.x >> 5;
    if (lane == 0) red[wid] = s;
    __syncthreads();
    if (wid == 0) {
        s = (lane < 8) ? red[lane] : 0.f;
#pragma unroll
        for (int o = 4; o > 0; o >>= 1) s += __shfl_xor_sync(0xffffffffu, s, o);
        if (lane == 0) red[0] = s;
    }
    __syncthreads();
    const float inv = rsqrtf(red[0] * (1.0f / (float)DMODEL) + 1e-6f);
    const float mk = mask ? mask[m] : 1.f;
    for (int i = threadIdx.x; i < DMODEL; i += 256)
        out[(size_t)m * DMODEL + i] = row[i] * inv * w[i] * mk;
}

// ---------------- causal depthwise conv1d ----------------
__global__ void conv_kernel(const float* __restrict__ zx,
                            const float* __restrict__ cw,
                            const float* __restrict__ cb,
                            float* __restrict__ xbc)
{
    const int m = blockIdx.x;
    const int t = m & (SEQ - 1);
    for (int c = threadIdx.x; c < CONVDIM; c += 256) {
        float acc = cb[c];
#pragma unroll
        for (int j = 0; j < DCONV; j++) {
            const int tt = t - (DCONV - 1) + j;
            if (tt >= 0)
                acc += cw[c * DCONV + j] *
                       zx[(size_t)(m - (DCONV - 1) + j) * DPROJ + DINNER + c];
        }
        xbc[(size_t)m * CONVDIM + c] = acc;
    }
}

// ---------------- sequential SSM scan + gating ----------------
#define CHK 8
#define TVALS 257
__global__ __launch_bounds__(256) void scan_kernel(
    const float* __restrict__ xbc, const float* __restrict__ zx,
    const float* __restrict__ Dv, const float* __restrict__ zb,
    float* __restrict__ gated)
{
    const int bh = blockIdx.x;
    const int b = bh >> 5;
    const int h = bh & 31;
    const int tid = threadIdx.x;
    const int p = tid >> 2;
    const int q = tid & 3;
    const int n0 = q << 4;

    __shared__ float sd[2][CHK * TVALS];

    int lts[9], loff[9], lkind[9], lsh[9];
    bool lvalid[9];
#pragma unroll
    for (int k = 0; k < 9; k++) {
        const int e = tid + k * 256;
        lvalid[k] = (e < CHK * TVALS);
        const int tsub = e / TVALS;
        const int j = e - tsub * TVALS;
        lts[k] = tsub; lsh[k] = e;
        if (j < 64)        { lkind[k] = 0; loff[k] = h * HEADDIM + j; }
        else if (j < 128)  { lkind[k] = 0; loff[k] = DINNER + h * DSTATE + (j - 64); }
        else if (j < 192)  { lkind[k] = 0; loff[k] = DINNER + NHEADS * DSTATE + h * DSTATE + (j - 128); }
        else if (j < 256)  { lkind[k] = 1; loff[k] = h * HEADDIM + (j - 192); }
        else               { lkind[k] = 2; loff[k] = 2 * DINNER + 2 * NHEADS * DSTATE + h; }
    }
#pragma unroll
    for (int k = 0; k < 9; k++) {
        if (lvalid[k]) {
            const size_t m = (size_t)b * SEQ + lts[k];
            float v;
            if (lkind[k] == 0) v = xbc[m * CONVDIM + loff[k]];
            else               v = zx[m * DPROJ + loff[k]];
            if (lkind[k] == 2) v = 1.f / (1.f + expf(v));
            sd[0][lsh[k]] = v;
        }
    }
    __syncthreads();

    float st[16];
#pragma unroll
    for (int i = 0; i < 16; i++) st[i] = 0.f;
    const float Dh = Dv[h];
    const float zbias = zb[h * HEADDIM + p];

    const int NC = SEQ / CHK;
    for (int c = 0; c < NC; c++) {
        const int cur = c & 1;
        const bool pre = (c + 1 < NC);
        float regv[9];
        if (pre) {
#pragma unroll
            for (int k = 0; k < 9; k++) {
                if (lvalid[k]) {
                    const size_t m = (size_t)b * SEQ + (c + 1) * CHK + lts[k];
                    float v;
                    if (lkind[k] == 0) v = xbc[m * CONVDIM + loff[k]];
                    else               v = zx[m * DPROJ + loff[k]];
                    if (lkind[k] == 2) v = 1.f / (1.f + expf(v));
                    regv[k] = v;
                }
            }
        }
        const float* dbase = sd[cur];
#pragma unroll
        for (int tsub = 0; tsub < CHK; tsub++) {
            const float* dd = dbase + tsub * TVALS;
            const float a  = dd[256];
            const float xv = dd[p];
            float y = 0.f;
#pragma unroll
            for (int i = 0; i < 16; i++) {
                st[i] = a * st[i] + xv * dd[64 + n0 + i];
                y = fmaf(st[i], dd[128 + n0 + i], y);
            }
            y += __shfl_xor_sync(0xffffffffu, y, 1);
            y += __shfl_xor_sync(0xffffffffu, y, 2);
            if (q == 0) {
                const size_t m = (size_t)b * SEQ + c * CHK + tsub;
                const float zval = dd[192 + p] + zbias;
                const float sig = 1.f / (1.f + expf(-zval));
                gated[m * DMODEL + h * HEADDIM + p] = (y + Dh * xv) * (zval * sig);
            }
        }
        if (pre) {
#pragma unroll
            for (int k = 0; k < 9; k++)
                if (lvalid[k]) sd[cur ^ 1][lsh[k]] = regv[k];
        }
        __syncthreads();
    }
}

// ---------------- silu(gate)*up in place ----------------
__global__ void silumul_kernel(float* __restrict__ g, const float* __restrict__ u, size_t n)
{
    size_t i = (size_t)blockIdx.x * blockDim.x + threadIdx.x;
    const size_t stride = (size_t)gridDim.x * blockDim.x;
    for (; i < n; i += stride) {
        const float x = g[i];
        g[i] = u[i] * x / (1.f + expf(-x));
    }
}

// ---------------- launcher ----------------
extern "C" void kernel_launch(void* const* d_in, const int* in_sizes, int n_in,
                              void* d_out, int out_size)
{
    (void)in_sizes; (void)n_in; (void)out_size;
    const float* hidden     = (const float*)d_in[0];
    const float* mask       = (const float*)d_in[1];
    const float* in_proj_w  = (const float*)d_in[2];
    const float* conv_w     = (const float*)d_in[3];
    const float* conv_b     = (const float*)d_in[4];
    const float* z_bias     = (const float*)d_in[5];
    const float* Dv         = (const float*)d_in[6];
    const float* out_proj_w = (const float*)d_in[7];
    const float* ln1_w      = (const float*)d_in[8];
    const float* ln2_w      = (const float*)d_in[9];
    const float* gate_w     = (const float*)d_in[10];
    const float* up_w       = (const float*)d_in[11];
    const float* down_w     = (const float*)d_in[12];
    float* out = (float*)d_out;

    float *xnorm, *zx, *xbc, *gated, *res2, *gatef, *upf;
    cudaGetSymbolAddress((void**)&xnorm, g_xnorm);
    cudaGetSymbolAddress((void**)&zx,    g_zx);
    cudaGetSymbolAddress((void**)&xbc,   g_xbc);
    cudaGetSymbolAddress((void**)&gated, g_gated);
    cudaGetSymbolAddress((void**)&res2,  g_res2);
    cudaGetSymbolAddress((void**)&gatef, g_gatef);
    cudaGetSymbolAddress((void**)&upf,   g_upf);

    cudaFuncSetAttribute(gemm_mma, cudaFuncAttributeMaxDynamicSharedMemorySize, GSMEM);

    // 1. rmsnorm(hidden, ln1) * mask
    rmsnorm_kernel<<<MROWS, 256>>>(hidden, ln1_w, mask, xnorm);

    // 2. zxbcdt = xnorm @ in_proj_w^T   (4096 x 8224 x 2048)
    gemm_mma<<<dim3(MROWS/128, (DPROJ + 127)/128), 256, GSMEM>>>(
        xnorm, in_proj_w, zx, nullptr, DPROJ, DMODEL, 0);

    // 3. conv + 4. scan (fused D*x + silu(z) gate)
    conv_kernel<<<MROWS, 256>>>(zx, conv_w, conv_b, xbc);
    scan_kernel<<<BATCH * NHEADS, 256>>>(xbc, zx, Dv, z_bias, gated);

    // 5. res2 = gated @ out_proj_w^T + hidden
    gemm_mma<<<dim3(MROWS/128, DMODEL/128), 256, GSMEM>>>(
        gated, out_proj_w, res2, hidden, DMODEL, DMODEL, 1);

    // 6. h2n = rmsnorm(res2, ln2)  (reuse xnorm buffer)
    rmsnorm_kernel<<<MROWS, 256>>>(res2, ln2_w, nullptr, xnorm);

    // 7/8. gate and up projections (4096 x 5504 x 2048)
    gemm_mma<<<dim3(MROWS/128, INTERSZ/128), 256, GSMEM>>>(
        xnorm, gate_w, gatef, nullptr, INTERSZ, DMODEL, 0);
    gemm_mma<<<dim3(MROWS/128, INTERSZ/128), 256, GSMEM>>>(
        xnorm, up_w, upf, nullptr, INTERSZ, DMODEL, 0);

    // 9. gate = silu(gate) * up
    silumul_kernel<<<8192, 256>>>(gatef, upf, (size_t)MROWS * INTERSZ);

    // 10. out = gate @ down_w^T + res2   (4096 x 2048 x 5504)
    gemm_mma<<<dim3(MROWS/128, DMODEL/128), 256, GSMEM>>>(
        gatef, down_w, out, res2, DMODEL, INTERSZ, 1);
}